// round 16
// baseline (speedup 1.0000x reference)
#include <cuda_runtime.h>
#include <cstdint>

#define BB 64
#define TT 4096
#define CC 51
#define DD 64
#define NTHREADS 128
#define LN_EPS 1e-5f

typedef unsigned long long ull;

// Packed fp32x2 FMA (Blackwell FFMA2 — PTX-only)
#define FMA2(d, a, b, c) \
    asm("fma.rn.f32x2 %0, %1, %2, %3;" : "=l"(d) : "l"(a), "l"(b), "l"(c))
// Build (f,f) register pair from one float (MOV pair, ALU pipe)
#define DUPF(d, f) \
    asm("mov.b64 %0, {%1, %1};" : "=l"(d) : "f"(f))

static __device__ __forceinline__ float lo32(ull v) { return __uint_as_float((unsigned)v); }
static __device__ __forceinline__ float hi32(ull v) { return __uint_as_float((unsigned)(v >> 32)); }
static __device__ __forceinline__ ull pack2(float x, float y) {
    return (ull)__float_as_uint(x) | ((ull)__float_as_uint(y) << 32);
}

static __device__ __forceinline__ int mask_val(const void* p, long i, int dt)
{
    if (dt == 1) return ((const int*)p)[i] != 0;
    if (dt == 2) return ((const float*)p)[i] != 0.0f;
    return ((const unsigned char*)p)[i] != 0;
}

// ---------------------------------------------------------------------------
// SMEM layout (bytes):
//   [0)      float xs[128][52]        un-duplicated x, column-compacted  = 26624
//   [26624)  ulonglong2 Wsh2[26][32]  compacted W col-pairs per-lane d   = 13312
//   [39936)  int cpos[52]   orig col -> compacted col (-1 if masked)
//   [40144)  int cmap[52]   compacted col -> orig col
//   [40352)  int ncp        compacted column count
// ---------------------------------------------------------------------------
#define SM_XS    0
#define SM_WD    26624
#define SM_CPOS  39936
#define SM_CMAP  40144
#define SM_NCP   40352
#define SM_TOTAL 40368

extern "C" __global__ void __launch_bounds__(NTHREADS, 3)
fused_proj_ln_kernel(const float* __restrict__ x,
                     const float* __restrict__ W,
                     const float* __restrict__ Wm,
                     const float* __restrict__ gamma,
                     const float* __restrict__ beta,
                     const void* __restrict__ time_mask,
                     const void* __restrict__ sensor_mask,
                     float* __restrict__ out)
{
    extern __shared__ char smem[];
    float*      xs   = (float*)(smem + SM_XS);        // [128][52]
    ulonglong2* Wsh2 = (ulonglong2*)(smem + SM_WD);   // [26][32]
    int*        cpos = (int*)(smem + SM_CPOS);
    int*        cmap = (int*)(smem + SM_CMAP);
    int*        ncp  = (int*)(smem + SM_NCP);

    const int tid  = threadIdx.x;
    const int lane = tid & 31;
    const int wid  = tid >> 5;

    const int  b    = blockIdx.x >> 5;            // 32 tiles per batch
    const int  tb   = (blockIdx.x & 31) * 128;
    const long tok0 = (long)b * TT + tb;

    // ---- phase 0: x LDG batch (MLP-13) + in-block dtype detection ----
    const float4* xg4 = (const float4*)(x + tok0 * CC);   // 1632 float4 / tile
    float4 vv[13];
#pragma unroll
    for (int k = 0; k < 12; ++k) vv[k] = xg4[tid + 128 * k];
    const bool tail = tid < 96;
    if (tail) vv[12] = xg4[1536 + tid];

    const unsigned dw = ((const unsigned*)time_mask)[tid];
    const int dtI = __syncthreads_and(dw <= 1u);
    const int dtF = __syncthreads_and(dw == 0u || dw == 0x3f800000u);
    const int dt  = dtI ? 1 : (dtF ? 2 : 0);

    // ---- phase 1: time-mask ballot + warp-0 compaction-map build ----
    const int un = !mask_val(time_mask, tok0 + tid, dt);  // warp wid owns tokens wid*32..+31
    const unsigned um = __ballot_sync(0xffffffffu, un);

    // CC=51 > 32 lanes: each lane handles columns lane and lane+32.
    if (wid == 0) {
        const long sbase = (long)b * CC;
        int m0 = mask_val(sensor_mask, sbase + lane, dt);            // c = lane (0..31)
        int m1 = (lane + 32 < CC)
               ? mask_val(sensor_mask, sbase + lane + 32, dt) : 1;   // c = lane+32 (32..50)
        const unsigned keep0 = __ballot_sync(0xffffffffu, !m0);
        const unsigned keep1 = __ballot_sync(0xffffffffu, !m1);
        const int n0 = __popc(keep0);
        const unsigned below = (1u << lane) - 1u;

        const int p0 = __popc(keep0 & below);
        cpos[lane] = m0 ? -1 : p0;
        if (!m0) cmap[p0] = lane;

        if (lane + 32 < CC) {
            const int p1 = n0 + __popc(keep1 & below);
            cpos[lane + 32] = m1 ? -1 : p1;
            if (!m1) cmap[p1] = lane + 32;
        }
        if (lane == 0) *ncp = n0 + __popc(keep1);
    }
    __syncthreads();                              // #1: cpos/cmap/ncp ready

    const int nc = *ncp;
    const int NG = (nc + 3) >> 2;                 // 4-column groups (block-uniform)

    // ---- phase 2: W staging (compacted), pad zero, x scatter, bias/cvec ----
    // Wsh2[j] holds compacted col-pair (2j, 2j+1); zero past nc.
    for (int j = wid; j < 26; j += 4) {
        int c0 = 2 * j, c1 = 2 * j + 1;
        ull w0 = (c0 < nc) ? *(const ull*)(W + cmap[c0] * DD + 2 * lane) : 0ull;
        ull w1 = (c1 < nc) ? *(const ull*)(W + cmap[c1] * DD + 2 * lane) : 0ull;
        ulonglong2 t; t.x = w0; t.y = w1;
        Wsh2[j * 32 + lane] = t;
    }

    // zero pad columns [nc, 4*NG) of this thread's row
    for (int j = nc; j < 4 * NG; ++j) xs[tid * 52 + j] = 0.0f;

    // compacted x scatter: 4 scalar STS per float4 (cpos lookup each)
#pragma unroll
    for (int k = 0; k < 13; ++k) {
        if (k < 12 || tail) {
            float4 v = vv[k];
            int idx = 4 * tid + 512 * k;
            int t = idx / CC;
            int c = idx - t * CC;
            int j;
            j = cpos[c]; if (j >= 0) xs[t * 52 + j] = v.x;
            if (++c == CC) { c = 0; ++t; }
            j = cpos[c]; if (j >= 0) xs[t * 52 + j] = v.y;
            if (++c == CC) { c = 0; ++t; }
            j = cpos[c]; if (j >= 0) xs[t * 52 + j] = v.z;
            if (++c == CC) { c = 0; ++t; }
            j = cpos[c]; if (j >= 0) xs[t * 52 + j] = v.w;
        }
    }

    // per-batch bias (sum Wm over sensor-masked c) + global Wm sum
    float2 wsA = make_float2(0.f, 0.f), wsB = make_float2(0.f, 0.f);
    float2 bsA = make_float2(0.f, 0.f), bsB = make_float2(0.f, 0.f);
#pragma unroll
    for (int c = 0; c < CC; ++c) {
        float2 wm = *(const float2*)(Wm + c * DD + 2 * lane);
        const bool msk = (cpos[c] < 0);
        if (c & 1) { wsB.x += wm.x; wsB.y += wm.y; if (msk) { bsB.x += wm.x; bsB.y += wm.y; } }
        else       { wsA.x += wm.x; wsA.y += wm.y; if (msk) { bsA.x += wm.x; bsA.y += wm.y; } }
    }
    const float2 wsum = make_float2(wsA.x + wsB.x, wsA.y + wsB.y);
    const ull    bll  = pack2(bsA.x + bsB.x, bsA.y + bsB.y);

    const float2 g2 = *(const float2*)(gamma + 2 * lane);
    const float2 b2 = *(const float2*)(beta  + 2 * lane);

    // constant row for time-masked tokens: LN(sum_all_c Wm)
    float2 cvec;
    {
        float s = wsum.x + wsum.y;
        float q = wsum.x * wsum.x + wsum.y * wsum.y;
#pragma unroll
        for (int o = 16; o > 0; o >>= 1) {
            s += __shfl_xor_sync(0xffffffffu, s, o);
            q += __shfl_xor_sync(0xffffffffu, q, o);
        }
        float mu = s * (1.0f / 64.0f);
        float r  = rsqrtf(fmaf(-mu, mu, q * (1.0f / 64.0f)) + LN_EPS);
        cvec.x = fmaf((wsum.x - mu) * r, g2.x, b2.x);
        cvec.y = fmaf((wsum.y - mu) * r, g2.y, b2.y);
    }

    // time-masked tokens: predicated constant-row stores
    float2* out2 = (float2*)out;
    const int  rbase = wid * 32;
    const long otok  = tok0 + rbase;
    {
        unsigned mm = ~um;
        float2* ob = out2 + otok * 32 + lane;
#pragma unroll
        for (int r = 0; r < 32; ++r)
            if ((mm >> r) & 1u) ob[r * 32] = cvec;
    }
    __syncthreads();                              // #2: xs + Wsh2 ready

    // ---- phase 3: mainloop — warp-compacted groups of 8 FFMA2 chains,
    //      uniform dynamic loop over NG compacted column-groups ----
    unsigned umw = um;
    while (umw) {
        int r0 = __ffs(umw) - 1; umw &= umw - 1;
        int r1 = r0, r2 = r0, r3 = r0, r4 = r0, r5 = r0, r6 = r0, r7 = r0;
        int nv = 1;
        if (umw) { r1 = __ffs(umw) - 1; umw &= umw - 1; nv = 2; }
        if (umw) { r2 = __ffs(umw) - 1; umw &= umw - 1; nv = 3; }
        if (umw) { r3 = __ffs(umw) - 1; umw &= umw - 1; nv = 4; }
        if (umw) { r4 = __ffs(umw) - 1; umw &= umw - 1; nv = 5; }
        if (umw) { r5 = __ffs(umw) - 1; umw &= umw - 1; nv = 6; }
        if (umw) { r6 = __ffs(umw) - 1; umw &= umw - 1; nv = 7; }
        if (umw) { r7 = __ffs(umw) - 1; umw &= umw - 1; nv = 8; }

        const float* p0 = xs + (rbase + r0) * 52;
        const float* p1 = xs + (rbase + r1) * 52;
        const float* p2 = xs + (rbase + r2) * 52;
        const float* p3 = xs + (rbase + r3) * 52;
        const float* p4 = xs + (rbase + r4) * 52;
        const float* p5 = xs + (rbase + r5) * 52;
        const float* p6 = xs + (rbase + r6) * 52;
        const float* p7 = xs + (rbase + r7) * 52;

        ull a0 = bll, a1 = bll, a2 = bll, a3 = bll;
        ull a4 = bll, a5 = bll, a6 = bll, a7 = bll;
        ull d0, d1, d2, d3, d4, d5, d6, d7;

#pragma unroll 1
        for (int gi = 0; gi < NG; ++gi) {
            ulonglong2 wA = Wsh2[(2 * gi) * 32 + lane];      // cols 4gi, 4gi+1
            ulonglong2 wB = Wsh2[(2 * gi + 1) * 32 + lane];  // cols 4gi+2, 4gi+3
            float4 u0 = *(const float4*)(p0 + 4 * gi);       // broadcast LDS.128
            float4 u1 = *(const float4*)(p1 + 4 * gi);
            float4 u2 = *(const float4*)(p2 + 4 * gi);
            float4 u3 = *(const float4*)(p3 + 4 * gi);
            float4 u4 = *(const float4*)(p4 + 4 * gi);
            float4 u5 = *(const float4*)(p5 + 4 * gi);
            float4 u6 = *(const float4*)(p6 + 4 * gi);
            float4 u7 = *(const float4*)(p7 + 4 * gi);

            DUPF(d0, u0.x); FMA2(a0, d0, wA.x, a0);
            DUPF(d1, u1.x); FMA2(a1, d1, wA.x, a1);
            DUPF(d2, u2.x); FMA2(a2, d2, wA.x, a2);
            DUPF(d3, u3.x); FMA2(a3, d3, wA.x, a3);
            DUPF(d4, u4.x); FMA2(a4, d4, wA.x, a4);
            DUPF(d5, u5.x); FMA2(a5, d5, wA.x, a5);
            DUPF(d6, u6.x); FMA2(a6, d6, wA.x, a6);
            DUPF(d7, u7.x); FMA2(a7, d7, wA.x, a7);

            DUPF(d0, u0.y); FMA2(a0, d0, wA.y, a0);
            DUPF(d1, u1.y); FMA2(a1, d1, wA.y, a1);
            DUPF(d2, u2.y); FMA2(a2, d2, wA.y, a2);
            DUPF(d3, u3.y); FMA2(a3, d3, wA.y, a3);
            DUPF(d4, u4.y); FMA2(a4, d4, wA.y, a4);
            DUPF(d5, u5.y); FMA2(a5, d5, wA.y, a5);
            DUPF(d6, u6.y); FMA2(a6, d6, wA.y, a6);
            DUPF(d7, u7.y); FMA2(a7, d7, wA.y, a7);

            DUPF(d0, u0.z); FMA2(a0, d0, wB.x, a0);
            DUPF(d1, u1.z); FMA2(a1, d1, wB.x, a1);
            DUPF(d2, u2.z); FMA2(a2, d2, wB.x, a2);
            DUPF(d3, u3.z); FMA2(a3, d3, wB.x, a3);
            DUPF(d4, u4.z); FMA2(a4, d4, wB.x, a4);
            DUPF(d5, u5.z); FMA2(a5, d5, wB.x, a5);
            DUPF(d6, u6.z); FMA2(a6, d6, wB.x, a6);
            DUPF(d7, u7.z); FMA2(a7, d7, wB.x, a7);

            DUPF(d0, u0.w); FMA2(a0, d0, wB.y, a0);
            DUPF(d1, u1.w); FMA2(a1, d1, wB.y, a1);
            DUPF(d2, u2.w); FMA2(a2, d2, wB.y, a2);
            DUPF(d3, u3.w); FMA2(a3, d3, wB.y, a3);
            DUPF(d4, u4.w); FMA2(a4, d4, wB.y, a4);
            DUPF(d5, u5.w); FMA2(a5, d5, wB.y, a5);
            DUPF(d6, u6.w); FMA2(a6, d6, wB.y, a6);
            DUPF(d7, u7.w); FMA2(a7, d7, wB.y, a7);
        }

        // ---- fused LN for 8 chains + guarded stores ----
        ull aa[8] = {a0, a1, a2, a3, a4, a5, a6, a7};
        int rr[8] = {r0, r1, r2, r3, r4, r5, r6, r7};
        float xv[8], yv[8], sv[8], qv[8];
#pragma unroll
        for (int k = 0; k < 8; ++k) {
            xv[k] = lo32(aa[k]); yv[k] = hi32(aa[k]);
            sv[k] = xv[k] + yv[k];
            qv[k] = xv[k] * xv[k] + yv[k] * yv[k];
        }
#pragma unroll
        for (int o = 16; o > 0; o >>= 1) {
#pragma unroll
            for (int k = 0; k < 8; ++k) {
                sv[k] += __shfl_xor_sync(0xffffffffu, sv[k], o);
                qv[k] += __shfl_xor_sync(0xffffffffu, qv[k], o);
            }
        }
#pragma unroll
        for (int k = 0; k < 8; ++k) {
            float mu = sv[k] * (1.f / 64.f);
            float r  = rsqrtf(fmaf(-mu, mu, qv[k] * (1.f / 64.f)) + LN_EPS);
            if (k < nv) {
                float2 o2;
                o2.x = fmaf((xv[k] - mu) * r, g2.x, b2.x);
                o2.y = fmaf((yv[k] - mu) * r, g2.y, b2.y);
                out2[(otok + rr[k]) * 32 + lane] = o2;
            }
        }
    }
}

extern "C" void kernel_launch(void* const* d_in, const int* in_sizes, int n_in,
                              void* d_out, int out_size)
{
    const float* x     = (const float*)d_in[0];
    const float* W     = (const float*)d_in[1];
    const float* Wm    = (const float*)d_in[2];
    const float* gamma = (const float*)d_in[3];
    const float* beta  = (const float*)d_in[4];
    const void*  tmask = d_in[5];
    const void*  smask = d_in[6];

    (void)in_sizes; (void)n_in; (void)out_size;

    cudaFuncSetAttribute(fused_proj_ln_kernel,
                         cudaFuncAttributeMaxDynamicSharedMemorySize, SM_TOTAL);

    const int nblocks = BB * (TT / 128);   // 2048; single launch
    fused_proj_ln_kernel<<<nblocks, NTHREADS, SM_TOTAL>>>(
        x, W, Wm, gamma, beta, tmask, smask, (float*)d_out);
}